// round 1
// baseline (speedup 1.0000x reference)
#include <cuda_runtime.h>
#include <cuda_bf16.h>

// Piecewise-linear log-sigmoid approximation.
// vals: [64,2048,2048] fp32 (268,435,456 elements), x/y: 65-entry tables.
// Uniform breakpoints: x[i] = -10 + i*0.3125  =>  idx = clamp((int)(v*3.2+32), 0, 63)
// out = v              if v <  x[0]
//       0              if v >= x[64]
//       y[i] + (v - x[i]) * slope[i]   otherwise
//
// Memory-bound: 2 GiB traffic => ~300us floor on GB300 HBM3e.

#define NBP 65
#define THREADS 256

__global__ __launch_bounds__(THREADS)
void logsig_pwl_kernel(const float* __restrict__ vals,
                       const float* __restrict__ xt,
                       const float* __restrict__ yt,
                       float* __restrict__ out,
                       long long n4)   // number of float4 elements
{
    __shared__ float s_x[NBP];
    __shared__ float s_y[NBP];
    __shared__ float s_slope[NBP - 1];

    int tid = threadIdx.x;
    if (tid < NBP) {
        s_x[tid] = xt[tid];
        s_y[tid] = yt[tid];
    }
    __syncthreads();
    if (tid < NBP - 1) {
        s_slope[tid] = (s_y[tid + 1] - s_y[tid]) / (s_x[tid + 1] - s_x[tid]);
    }
    __syncthreads();

    const float x_lo_bound = s_x[0];        // -10
    const float x_hi_bound = s_x[NBP - 1];  // +10
    // idx mapping: t = v*3.2 + 32  (1/h = 3.2, -x0/h = 32)
    const float INV_H = 3.2f;
    const float OFFS  = 32.0f;

    long long i = (long long)blockIdx.x * THREADS + tid;
    if (i >= n4) return;

    const float4* in4 = (const float4*)vals;
    float4* out4 = (float4*)out;

    float4 v = in4[i];
    float r[4];
    float vv[4] = {v.x, v.y, v.z, v.w};

    #pragma unroll
    for (int k = 0; k < 4; k++) {
        float val = vv[k];
        float t = fmaf(val, INV_H, OFFS);
        int idx = (int)t;                    // trunc; negatives clamped below
        idx = max(0, min(idx, NBP - 2));
        float interp = fmaf(val - s_x[idx], s_slope[idx], s_y[idx]);
        float res = (val < x_lo_bound) ? val
                  : (val >= x_hi_bound) ? 0.0f
                  : interp;
        r[k] = res;
    }

    float4 o;
    o.x = r[0]; o.y = r[1]; o.z = r[2]; o.w = r[3];
    out4[i] = o;
}

// Tail kernel for n not divisible by 4 (not expected here, but safe).
__global__ void logsig_pwl_tail(const float* __restrict__ vals,
                                const float* __restrict__ xt,
                                const float* __restrict__ yt,
                                float* __restrict__ out,
                                long long start, long long n)
{
    long long i = start + blockIdx.x * blockDim.x + threadIdx.x;
    if (i >= n) return;
    float x0 = xt[0];
    float xK = xt[NBP - 1];
    float val = vals[i];
    float t = fmaf(val, 3.2f, 32.0f);
    int idx = (int)t;
    idx = max(0, min(idx, NBP - 2));
    float x_lo = xt[idx];
    float y_lo = yt[idx];
    float slope = (yt[idx + 1] - y_lo) / (xt[idx + 1] - x_lo);
    float interp = fmaf(val - x_lo, slope, y_lo);
    out[i] = (val < x0) ? val : (val >= xK) ? 0.0f : interp;
}

extern "C" void kernel_launch(void* const* d_in, const int* in_sizes, int n_in,
                              void* d_out, int out_size)
{
    const float* vals = (const float*)d_in[0];
    const float* xt   = (const float*)d_in[1];
    const float* yt   = (const float*)d_in[2];
    float* out        = (float*)d_out;

    long long n = (long long)in_sizes[0];
    long long n4 = n / 4;
    long long rem = n - n4 * 4;

    if (n4 > 0) {
        long long blocks = (n4 + THREADS - 1) / THREADS;
        logsig_pwl_kernel<<<(unsigned)blocks, THREADS>>>(vals, xt, yt, out, n4);
    }
    if (rem > 0) {
        logsig_pwl_tail<<<1, 256>>>(vals, xt, yt, out, n4 * 4, n);
    }
}

// round 2
// speedup vs baseline: 1.3094x; 1.3094x over previous
#include <cuda_runtime.h>
#include <cuda_bf16.h>

// Piecewise-linear log-sigmoid approximation (table interp), GB300 sm_103a.
// vals: [64,2048,2048] fp32 (268,435,456 elems), x/y: 65-entry uniform tables.
//   x[i] = -10 + i*0.3125 (step 5/16, exact in fp32)
//   idx  = clamp((int)(v*3.2 + 32), 0, 63)
//   out  = v                          if v <  x[0]
//          0                          if v >= x[64]
//          y[i] + (v - x[i])*slope[i] otherwise
//
// R1: single float2 LDS gather per element (y_lo, slope), analytic x_lo,
//     4x float4 per thread for MLP=4. Pure HBM-streaming target ~320us.

#define NBP 65
#define THREADS 256
#define V4_PER_THREAD 4   // float4s per thread -> 64B load + 64B store per thread

__global__ __launch_bounds__(THREADS)
void logsig_pwl_kernel(const float4* __restrict__ in4,
                       const float*  __restrict__ xt,
                       const float*  __restrict__ yt,
                       float4* __restrict__ out4,
                       long long n4)   // number of float4 elements
{
    __shared__ float2 s_seg[NBP - 1];   // (y_lo, slope) per segment
    __shared__ float  s_bounds[2];

    const int tid = threadIdx.x;
    if (tid < NBP - 1) {
        float xl = xt[tid], xh = xt[tid + 1];
        float yl = yt[tid], yh = yt[tid + 1];
        s_seg[tid] = make_float2(yl, (yh - yl) / (xh - xl));
    }
    if (tid == 0) { s_bounds[0] = xt[0]; s_bounds[1] = xt[NBP - 1]; }
    __syncthreads();

    const float x_lo_bound = s_bounds[0];   // -10
    const float x_hi_bound = s_bounds[1];   // +10
    const float INV_H = 3.2f;
    const float OFFS  = 32.0f;
    const float H     = 0.3125f;            // 5/16, exact
    const float X0    = -10.0f;

    long long base = (long long)blockIdx.x * (THREADS * V4_PER_THREAD) + tid;

    float4 v[V4_PER_THREAD];
    bool   ok[V4_PER_THREAD];

    // Batch the loads up front -> 4 LDG.128 in flight (MLP=4)
    #pragma unroll
    for (int j = 0; j < V4_PER_THREAD; j++) {
        long long i = base + (long long)j * THREADS;
        ok[j] = (i < n4);
        if (ok[j]) v[j] = in4[i];
    }

    #pragma unroll
    for (int j = 0; j < V4_PER_THREAD; j++) {
        if (!ok[j]) continue;
        float vv[4] = {v[j].x, v[j].y, v[j].z, v[j].w};
        float r[4];
        #pragma unroll
        for (int k = 0; k < 4; k++) {
            float val = vv[k];
            int idx = (int)fmaf(val, INV_H, OFFS);
            idx = max(0, min(idx, NBP - 2));
            float2 seg = s_seg[idx];                    // one LDS.64
            float x_lo = fmaf((float)idx, H, X0);       // exact, matches xt[idx]
            float interp = fmaf(val - x_lo, seg.y, seg.x);
            r[k] = (val <  x_lo_bound) ? val
                 : (val >= x_hi_bound) ? 0.0f
                 : interp;
        }
        float4 o; o.x = r[0]; o.y = r[1]; o.z = r[2]; o.w = r[3];
        long long i = base + (long long)j * THREADS;
        out4[i] = o;
    }
}

// Tail kernel for n not divisible by 4 (not expected for this shape, but safe).
__global__ void logsig_pwl_tail(const float* __restrict__ vals,
                                const float* __restrict__ xt,
                                const float* __restrict__ yt,
                                float* __restrict__ out,
                                long long start, long long n)
{
    long long i = start + blockIdx.x * blockDim.x + threadIdx.x;
    if (i >= n) return;
    float x0 = xt[0];
    float xK = xt[NBP - 1];
    float val = vals[i];
    int idx = (int)fmaf(val, 3.2f, 32.0f);
    idx = max(0, min(idx, NBP - 2));
    float x_lo = xt[idx];
    float y_lo = yt[idx];
    float slope = (yt[idx + 1] - y_lo) / (xt[idx + 1] - x_lo);
    float interp = fmaf(val - x_lo, slope, y_lo);
    out[i] = (val < x0) ? val : (val >= xK) ? 0.0f : interp;
}

extern "C" void kernel_launch(void* const* d_in, const int* in_sizes, int n_in,
                              void* d_out, int out_size)
{
    const float* vals = (const float*)d_in[0];
    const float* xt   = (const float*)d_in[1];
    const float* yt   = (const float*)d_in[2];
    float* out        = (float*)d_out;

    long long n  = (long long)in_sizes[0];
    long long n4 = n / 4;
    long long rem = n - n4 * 4;

    if (n4 > 0) {
        long long perBlock = (long long)THREADS * V4_PER_THREAD;
        long long blocks = (n4 + perBlock - 1) / perBlock;
        logsig_pwl_kernel<<<(unsigned)blocks, THREADS>>>(
            (const float4*)vals, xt, yt, (float4*)out, n4);
    }
    if (rem > 0) {
        logsig_pwl_tail<<<1, 256>>>(vals, xt, yt, out, n4 * 4, n);
    }
}